// round 9
// baseline (speedup 1.0000x reference)
#include <cuda_runtime.h>

// LSTM2: 2-layer LSTM, B=1024, T=1024, H=64, input dim 1, output 1/step.
// Persistent-RNN: 128 CTAs x 512 threads, 8 batch rows per CTA.
// Thread = (unit n, gate-half gh, k-quarter kq); lane = gh*16 + kq*4 + nl.
// Each thread: 2 gates x 8 rows x 16 k (strided k-ownership: k = 16i+4kq+j)
// with f32x2 FMAs. 2-level kq butterfly (xor4, xor8) -> rows {kq, kq+4};
// cross-gate-half exchange (xor16) completes the cell update:
//   gh0: sigma(i), sigma(f), cell state; gh1: tanh(g), sigma(o), h store.
// Weight pitch 72 (conflict-free octets), h rows contiguous 64 floats pitch 72
// (h loads hit one 64B window per instr -> ~1 wavefront).

namespace {

constexpr int T_LEN = 1024;
constexpr int RPC   = 8;             // batch rows per CTA
constexpr int NTH   = 512;           // threads per CTA
constexpr int GRID  = 1024 / RPC;    // 128

constexpr int WP    = 72;            // weight row pitch (floats)
constexpr int HP    = 72;            // h row pitch (floats)
constexpr int HB    = RPC * HP;      // 576 floats per h buffer

constexpr int SMEM_FLOATS = 3 * 256 * WP + 64 + 4 * HB + 16;
constexpr int SMEM_BYTES  = SMEM_FLOATS * 4;   // 230720 B

typedef unsigned long long u64;

__device__ __forceinline__ u64 fma2(u64 a, u64 b, u64 c) {
    u64 d;
    asm("fma.rn.f32x2 %0, %1, %2, %3;" : "=l"(d) : "l"(a), "l"(b), "l"(c));
    return d;
}
__device__ __forceinline__ float red2(u64 a) {
    return __uint_as_float((unsigned)a) + __uint_as_float((unsigned)(a >> 32));
}
__device__ __forceinline__ float tanh_f(float v) {
    float r;
    asm("tanh.approx.f32 %0, %1;" : "=f"(r) : "f"(v));
    return r;
}
__device__ __forceinline__ float sigm(float v) {
    return fmaf(tanh_f(0.5f * v), 0.5f, 0.5f);
}
__device__ __forceinline__ ulonglong2 ld2(const float* p) {
    return *(const ulonglong2*)p;
}

// Reduce 8 row-partials over the 4 kq lanes (lane bits 2,3).
// Lane with quarter kq ends with fully-summed rows {kq, kq+4} in (vA, vB).
__device__ __forceinline__ void bfly(const float pr[8], int kb0, int kb1,
                                     float& vA, float& vB) {
    float v0 = (kb0 ? pr[1] : pr[0]) + __shfl_xor_sync(~0u, kb0 ? pr[0] : pr[1], 4);
    float v1 = (kb0 ? pr[3] : pr[2]) + __shfl_xor_sync(~0u, kb0 ? pr[2] : pr[3], 4);
    float v2 = (kb0 ? pr[5] : pr[4]) + __shfl_xor_sync(~0u, kb0 ? pr[4] : pr[5], 4);
    float v3 = (kb0 ? pr[7] : pr[6]) + __shfl_xor_sync(~0u, kb0 ? pr[6] : pr[7], 4);
    vA = (kb1 ? v1 : v0) + __shfl_xor_sync(~0u, kb1 ? v0 : v1, 8);
    vB = (kb1 ? v3 : v2) + __shfl_xor_sync(~0u, kb1 ? v2 : v3, 8);
}

} // namespace

__global__ void __launch_bounds__(NTH, 1)
lstm2_kernel(const float* __restrict__ x,
             const float* __restrict__ w_ih1, const float* __restrict__ w_hh1,
             const float* __restrict__ b_ih1, const float* __restrict__ b_hh1,
             const float* __restrict__ w_ih2, const float* __restrict__ w_hh2,
             const float* __restrict__ b_ih2, const float* __restrict__ b_hh2,
             const float* __restrict__ w_lin, const float* __restrict__ b_lin,
             float* __restrict__ out)
{
    extern __shared__ float sm[];
    float* sWh1 = sm;                    // [256][72]
    float* sWi2 = sWh1 + 256 * WP;       // [256][72]
    float* sWh2 = sWi2 + 256 * WP;       // [256][72]
    float* sWl  = sWh2 + 256 * WP;       // [64]
    float* sH1  = sWl + 64;              // [2][8][72]
    float* sH2  = sH1 + 2 * HB;          // [2][8][72]
    float* sX   = sH2 + 2 * HB;          // [2][8]

    const int tid = threadIdx.x;
    const int rowbase = blockIdx.x * RPC;

    // ---- load weights into padded SMEM ----
    for (int i = tid; i < 256 * 64; i += NTH) {
        int j = i >> 6, k = i & 63;
        int off = j * WP + k;
        sWh1[off] = w_hh1[i];
        sWi2[off] = w_ih2[i];
        sWh2[off] = w_hh2[i];
    }
    if (tid < 64) sWl[tid] = w_lin[tid];
    for (int i = tid; i < 4 * HB; i += NTH) sH1[i] = 0.f;   // zeros h1 AND h2
    if (tid < RPC) sX[tid] = x[(rowbase + tid) * T_LEN];
    __syncthreads();

    // thread mapping: lane = gh*16 + kq*4 + nl; n = wid*4 + nl
    const int lid = tid & 31;
    const int wid = tid >> 5;            // 0..15
    const int nl  = lid & 3;
    const int kq  = (lid >> 2) & 3;
    const int gh  = lid >> 4;            // gate-half: 0 -> {i,f}, 1 -> {g,o}
    const int n   = (wid << 2) | nl;     // 0..63
    const int kq4 = kq * 4;
    const int kb0 = kq & 1, kb1 = (kq >> 1) & 1;
    const int rA = kq, rB = kq + 4;      // rows this lane finalizes

    const int ga = n + (gh ? 128 : 0);   // gate-a row (i or g)
    const int gb = ga + 64;              // gate-b row (f or o)

    // per-thread constants from GMEM (once)
    const float b1a = b_ih1[ga] + b_hh1[ga];
    const float b1b = b_ih1[gb] + b_hh1[gb];
    const float b2a = b_ih2[ga] + b_hh2[ga];
    const float b2b = b_ih2[gb] + b_hh2[gb];
    const float wxa = w_ih1[ga], wxb = w_ih1[gb];
    const float blin = b_lin[0];
    // activation of gate-a: gh0 (i): sigma = 0.5*tanh(0.5x)+0.5 ; gh1 (g): tanh
    const float sa = gh ? 1.0f : 0.5f;
    const float da = gh ? 0.0f : 0.5f;

    // weight base pointers (this thread's 2 gate rows, k-quarter stride slots)
    const float* W1a = sWh1 + ga * WP + kq4;
    const float* W1b = sWh1 + gb * WP + kq4;
    const float* Ua  = sWi2 + ga * WP + kq4;
    const float* Ub  = sWi2 + gb * WP + kq4;
    const float* Va  = sWh2 + ga * WP + kq4;
    const float* Vb  = sWh2 + gb * WP + kq4;

    // persistent cell state (meaningful on gh0 lanes; junk-but-bounded on gh1)
    float c1a = 0.f, c1b = 0.f, c2a = 0.f, c2b = 0.f;

    for (int t = 0; t < T_LEN; ++t) {
        const int p = t & 1, q = p ^ 1;

        // prefetch next x (hidden under compute)
        float xn = 0.f;
        if (tid < RPC) {
            int tn = (t + 1 < T_LEN) ? (t + 1) : t;
            xn = x[(rowbase + tid) * T_LEN + tn];
        }

        // ============ layer 1: 2 gates x 8 rows over strided k-quarter ============
        {
            const float* hb = sH1 + p * HB + kq4;
            u64 aA[8] = {}, aB[8] = {};
            #pragma unroll
            for (int i = 0; i < 4; ++i) {
                const int io = i * 16;
                ulonglong2 wa = ld2(W1a + io), wb = ld2(W1b + io);
                #pragma unroll
                for (int r = 0; r < 8; ++r) {
                    ulonglong2 hv = ld2(hb + r * HP + io);
                    aA[r] = fma2(wa.x, hv.x, aA[r]); aA[r] = fma2(wa.y, hv.y, aA[r]);
                    aB[r] = fma2(wb.x, hv.x, aB[r]); aB[r] = fma2(wb.y, hv.y, aB[r]);
                }
            }
            float prA[8], prB[8];
            #pragma unroll
            for (int r = 0; r < 8; ++r) { prA[r] = red2(aA[r]); prB[r] = red2(aB[r]); }
            float vaA, vaB, vbA, vbB;
            bfly(prA, kb0, kb1, vaA, vaB);
            bfly(prB, kb0, kb1, vbA, vbB);

            const float xsA = sX[p * RPC + rA];
            const float xsB = sX[p * RPC + rB];
            // gate-a: gh0 -> sigma(i), gh1 -> tanh(g); gate-b: sigma (f / o)
            float actaA = fmaf(tanh_f(sa * (fmaf(wxa, xsA, b1a) + vaA)), sa, da);
            float actbA = sigm(fmaf(wxb, xsA, b1b) + vbA);
            float actaB = fmaf(tanh_f(sa * (fmaf(wxa, xsB, b1a) + vaB)), sa, da);
            float actbB = sigm(fmaf(wxb, xsB, b1b) + vbB);
            // exchange gate-a across halves: gh0 receives gc, gh1 receives ii
            float e1A = __shfl_xor_sync(~0u, actaA, 16);
            float e1B = __shfl_xor_sync(~0u, actaB, 16);
            // gh0: c = f*c + i*gc  (gh1 computes bounded junk)
            c1a = actbA * c1a + actaA * e1A;
            c1b = actbB * c1b + actaB * e1B;
            float thA = __shfl_xor_sync(~0u, tanh_f(c1a), 16);  // gh1 gets tanh(c)
            float thB = __shfl_xor_sync(~0u, tanh_f(c1b), 16);
            if (gh) {
                sH1[q * HB + rA * HP + n] = actbA * thA;  // o * tanh(c)
                sH1[q * HB + rB * HP + n] = actbB * thB;
            }
        }
        if (tid < RPC) sX[q * RPC + tid] = xn;
        __syncthreads();   // h1[q] + x[q] published

        // ============ layer 2: U*h1[q] + V*h2[p] ============
        {
            u64 aA[8] = {}, aB[8] = {};
            {
                const float* hb = sH1 + q * HB + kq4;
                #pragma unroll
                for (int i = 0; i < 4; ++i) {
                    const int io = i * 16;
                    ulonglong2 wa = ld2(Ua + io), wb = ld2(Ub + io);
                    #pragma unroll
                    for (int r = 0; r < 8; ++r) {
                        ulonglong2 hv = ld2(hb + r * HP + io);
                        aA[r] = fma2(wa.x, hv.x, aA[r]); aA[r] = fma2(wa.y, hv.y, aA[r]);
                        aB[r] = fma2(wb.x, hv.x, aB[r]); aB[r] = fma2(wb.y, hv.y, aB[r]);
                    }
                }
            }
            {
                const float* hb = sH2 + p * HB + kq4;
                #pragma unroll
                for (int i = 0; i < 4; ++i) {
                    const int io = i * 16;
                    ulonglong2 wa = ld2(Va + io), wb = ld2(Vb + io);
                    #pragma unroll
                    for (int r = 0; r < 8; ++r) {
                        ulonglong2 hv = ld2(hb + r * HP + io);
                        aA[r] = fma2(wa.x, hv.x, aA[r]); aA[r] = fma2(wa.y, hv.y, aA[r]);
                        aB[r] = fma2(wb.x, hv.x, aB[r]); aB[r] = fma2(wb.y, hv.y, aB[r]);
                    }
                }
            }
            float prA[8], prB[8];
            #pragma unroll
            for (int r = 0; r < 8; ++r) { prA[r] = red2(aA[r]); prB[r] = red2(aB[r]); }
            float vaA, vaB, vbA, vbB;
            bfly(prA, kb0, kb1, vaA, vaB);
            bfly(prB, kb0, kb1, vbA, vbB);

            float actaA = fmaf(tanh_f(sa * (b2a + vaA)), sa, da);
            float actbA = sigm(b2b + vbA);
            float actaB = fmaf(tanh_f(sa * (b2a + vaB)), sa, da);
            float actbB = sigm(b2b + vbB);
            float e1A = __shfl_xor_sync(~0u, actaA, 16);
            float e1B = __shfl_xor_sync(~0u, actaB, 16);
            c2a = actbA * c2a + actaA * e1A;
            c2b = actbB * c2b + actaB * e1B;
            float thA = __shfl_xor_sync(~0u, tanh_f(c2a), 16);
            float thB = __shfl_xor_sync(~0u, tanh_f(c2b), 16);
            if (gh) {
                sH2[q * HB + rA * HP + n] = actbA * thA;
                sH2[q * HB + rB * HP + n] = actbB * thB;
            }
        }
        __syncthreads();   // h2[q] published

        // ====== output: warp w (w<8) reduces row w of h2[q] against w_lin ======
        if (wid < RPC) {
            const float* hr = sH2 + q * HB + wid * HP;
            float v = hr[lid] * sWl[lid] + hr[lid + 32] * sWl[lid + 32];
            #pragma unroll
            for (int off = 16; off; off >>= 1)
                v += __shfl_xor_sync(0xffffffffu, v, off);
            if (lid == 0) out[(rowbase + wid) * T_LEN + t] = v + blin;
        }
    }
}

extern "C" void kernel_launch(void* const* d_in, const int* in_sizes, int n_in,
                              void* d_out, int out_size)
{
    const float* x     = (const float*)d_in[0];
    const float* w_ih1 = (const float*)d_in[1];
    const float* w_hh1 = (const float*)d_in[2];
    const float* b_ih1 = (const float*)d_in[3];
    const float* b_hh1 = (const float*)d_in[4];
    const float* w_ih2 = (const float*)d_in[5];
    const float* w_hh2 = (const float*)d_in[6];
    const float* b_ih2 = (const float*)d_in[7];
    const float* b_hh2 = (const float*)d_in[8];
    const float* w_lin = (const float*)d_in[9];
    const float* b_lin = (const float*)d_in[10];

    cudaFuncSetAttribute(lstm2_kernel,
                         cudaFuncAttributeMaxDynamicSharedMemorySize, SMEM_BYTES);

    lstm2_kernel<<<GRID, NTH, SMEM_BYTES>>>(
        x, w_ih1, w_hh1, b_ih1, b_hh1,
        w_ih2, w_hh2, b_ih2, b_hh2,
        w_lin, b_lin, (float*)d_out);
}